// round 3
// baseline (speedup 1.0000x reference)
#include <cuda_runtime.h>
#include <cstdint>

#define BB 32
#define T_IN 512
#define NT 426
#define NC 1629          // 543*3
#define JF 53
#define XPART ((size_t)BB * NT * NC)   // 22,206,528

// bool-dtype mode: 0 = uint8, 1 = int32, 2 = float32
__device__ int g_mode;
__device__ int g_keptidx[BB][NT];
__device__ int g_K[BB];

__global__ void detect_kernel(const unsigned* __restrict__ w, int nwords) {
    __shared__ int s_bad01, s_anyf;
    if (threadIdx.x == 0) { s_bad01 = 0; s_anyf = 0; }
    __syncthreads();
    for (int i = threadIdx.x; i < nwords; i += blockDim.x) {
        unsigned v = w[i];
        if (v != 0u && v != 1u) atomicOr(&s_bad01, 1);
        if (v == 0x3F800000u)   atomicOr(&s_anyf, 1);
    }
    __syncthreads();
    if (threadIdx.x == 0)
        g_mode = s_bad01 ? (s_anyf ? 2 : 0) : 1;
}

__device__ __forceinline__ bool read_bool(const void* p, int i) {
    int m = g_mode;
    if (m == 0) return ((const unsigned char*)p)[i] != 0;
    if (m == 1) return ((const int*)p)[i] != 0;
    return ((const float*)p)[i] != 0.0f;
}

// One block per batch: warp-ballot prefix scan of keep_mask -> kept index list.
__global__ void kept_kernel(const void* __restrict__ keep) {
    int b = blockIdx.x;
    int t = threadIdx.x;                       // blockDim = 448 (14 warps)
    bool kb = (t < NT) ? read_bool(keep, b * NT + t) : false;
    unsigned bal = __ballot_sync(0xFFFFFFFFu, kb);
    int lane = t & 31, wid = t >> 5;
    int pre = __popc(bal & ((1u << lane) - 1u));
    __shared__ int wsum[14];
    if (lane == 0) wsum[wid] = __popc(bal);
    __syncthreads();
    int base = 0;
    for (int i = 0; i < wid; i++) base += wsum[i];
    if (kb) g_keptidx[b][base + pre] = t;
    if (t == 0) {
        int K = 0;
        for (int i = 0; i < 14; i++) K += wsum[i];
        g_K[b] = K;
    }
}

__global__ __launch_bounds__(256) void fused_kernel(
    const float* __restrict__ x,
    const void*  __restrict__ mask,
    const void*  __restrict__ keep,
    const float* __restrict__ bj,
    const float* __restrict__ noise,
    const float* __restrict__ sp,
    float* __restrict__ out)
{
    int bt = blockIdx.x;
    int b = bt / NT, t = bt % NT;

    __shared__ int   srows[8];
    __shared__ float sw[8];
    __shared__ int   snum;

    if (threadIdx.x == 0) {
        // ---- mask output ----
        int nidx = (int)floorf((float)t * (512.0f / 426.0f));
        if (nidx > T_IN - 1) nidx = T_IN - 1;
        bool kb = read_bool(keep, b * NT + t);
        bool mo = read_bool(mask, b * T_IN + nidx) && kb;
        out[XPART + (size_t)b * NT + t] = mo ? 1.0f : 0.0f;

        // ---- jitter (scale-then-lerp matches reference rounding) ----
        float jit = 0.0f;
        if (t > 0) {
            float sj = (float)t * (52.0f / 425.0f);
            int ij = (int)floorf(sj);
            if (ij > JF - 2) ij = JF - 2;
            if (ij < 0) ij = 0;
            float fj = sj - (float)ij;
            float j0 = bj[b * JF + ij]     * 0.02f;
            float j1 = bj[b * JF + ij + 1] * 0.02f;
            jit = j0 * (1.0f - fj) + j1 * fj;
        }

        // ---- build (row, weight) list ----
        int   rows[8];
        float wv[8];
        int n = 0;
        int K = g_K[b];

        auto push = [&](int r, float w) {
            for (int i = 0; i < n; i++)
                if (rows[i] == r) { wv[i] += w; return; }
            rows[n] = r; wv[n] = w; n++;
        };
        auto add_x1 = [&](int tau, float c) {
            float s = (float)tau * (511.0f / 425.0f);
            int i0 = (int)floorf(s);
            if (i0 > T_IN - 2) i0 = T_IN - 2;
            if (i0 < 0) i0 = 0;
            float f = s - (float)i0;
            push(i0,     c * (1.0f - f));
            push(i0 + 1, c * f);
        };
        auto add_x2 = [&](int tau, float c) {
            if (read_bool(keep, b * NT + tau)) {
                add_x1(tau, c);
            } else {
                float s = ((float)tau * (float)(K - 1)) / 425.0f;
                int r0 = (int)floorf(s);
                if (r0 > K - 2) r0 = K - 2;
                if (r0 < 0) r0 = 0;
                float fd = s - (float)r0;
                add_x1(g_keptidx[b][r0],     c * (1.0f - fd));
                add_x1(g_keptidx[b][r0 + 1], c * fd);
            }
        };

        if (t == 0) {
            add_x2(0, 1.0f);
        } else {
            add_x2(t,     1.0f + jit);
            add_x2(t - 1, -jit);
        }
        snum = n;
        for (int i = 0; i < n; i++) { srows[i] = rows[i]; sw[i] = wv[i]; }
    }
    __syncthreads();

    int n = snum;
    const float* xb = x     + (size_t)b * T_IN * NC;
    const float* nz = noise + ((size_t)b * NT + t) * NC;
    const float* sb = sp    + (size_t)b * NC;
    float*       ob = out   + ((size_t)b * NT + t) * NC;

    for (int e = threadIdx.x; e < NC; e += blockDim.x) {
        float acc = nz[e] * 0.01f + sb[e] * 0.005f;
        #pragma unroll 4
        for (int i = 0; i < n; i++)
            acc = fmaf(sw[i], xb[(size_t)srows[i] * NC + e], acc);
        ob[e] = acc;
    }
}

extern "C" void kernel_launch(void* const* d_in, const int* in_sizes, int n_in,
                              void* d_out, int out_size) {
    const float* x     = (const float*)d_in[0];
    const void*  mask  = d_in[1];
    const void*  keep  = d_in[2];
    const float* bj    = (const float*)d_in[3];
    const float* noise = (const float*)d_in[4];
    const float* sp    = (const float*)d_in[5];
    float* out = (float*)d_out;

    int keep_count = in_sizes[2];                 // BB*NT elements
    detect_kernel<<<1, 256>>>((const unsigned*)keep, keep_count / 4);
    kept_kernel<<<BB, 448>>>(keep);
    fused_kernel<<<BB * NT, 256>>>(x, mask, keep, bj, noise, sp, out);
}

// round 4
// speedup vs baseline: 1.4221x; 1.4221x over previous
#include <cuda_runtime.h>
#include <cstdint>

#define BB 32
#define T_IN 512
#define NT 426
#define NC 1629          // 543*3
#define JF 53
#define XPART ((size_t)BB * NT * NC)   // 22,206,528

// ---- device scratch (no allocation allowed) ----
__device__ int g_bad, g_anyf;
__device__ int g_K[BB];
__device__ int g_keptidx[BB][NT];
__device__ int   g_n[BB * NT];
__device__ int   g_rows[BB * NT][8];
__device__ float g_w[BB * NT][8];

__global__ void reset_kernel() { g_bad = 0; g_anyf = 0; }

// bool-dtype detection over the keep buffer's first keep_count/4 words:
// uint8-packed bools -> words like 0x01010101 (bad01, no f32 one) -> mode 0
// int32 0/1          -> all words 0/1                              -> mode 1
// float32 0/1        -> contains 0x3F800000                        -> mode 2
__global__ void detect_kernel(const unsigned* __restrict__ w, int nwords) {
    __shared__ int s_bad, s_anyf;
    if (threadIdx.x == 0) { s_bad = 0; s_anyf = 0; }
    __syncthreads();
    int lb = 0, lf = 0;
    for (int i = blockIdx.x * blockDim.x + threadIdx.x; i < nwords;
         i += gridDim.x * blockDim.x) {
        unsigned v = w[i];
        lb |= (v != 0u && v != 1u);
        lf |= (v == 0x3F800000u);
    }
    if (lb) atomicOr(&s_bad, 1);
    if (lf) atomicOr(&s_anyf, 1);
    __syncthreads();
    if (threadIdx.x == 0) {
        if (s_bad)  atomicOr(&g_bad, 1);
        if (s_anyf) atomicOr(&g_anyf, 1);
    }
}

__device__ __forceinline__ int get_mode() {
    return g_bad ? (g_anyf ? 2 : 0) : 1;
}

__device__ __forceinline__ bool read_bool_m(const void* p, int i, int m) {
    if (m == 0) return ((const unsigned char*)p)[i] != 0;
    if (m == 1) return ((const int*)p)[i] != 0;
    return ((const float*)p)[i] != 0.0f;
}

// One block per batch: warp-ballot prefix scan of keep_mask -> kept index list.
__global__ void kept_kernel(const void* __restrict__ keep) {
    __shared__ int s_mode;
    if (threadIdx.x == 0) s_mode = get_mode();
    __syncthreads();
    int m = s_mode;
    int b = blockIdx.x;
    int t = threadIdx.x;                       // blockDim = 448 (14 warps)
    bool kb = (t < NT) ? read_bool_m(keep, b * NT + t, m) : false;
    unsigned bal = __ballot_sync(0xFFFFFFFFu, kb);
    int lane = t & 31, wid = t >> 5;
    int pre = __popc(bal & ((1u << lane) - 1u));
    __shared__ int wsum[14];
    if (lane == 0) wsum[wid] = __popc(bal);
    __syncthreads();
    int base = 0;
    for (int i = 0; i < wid; i++) base += wsum[i];
    if (kb) g_keptidx[b][base + pre] = t;
    if (t == 0) {
        int K = 0;
        for (int i = 0; i < 14; i++) K += wsum[i];
        g_K[b] = K;
    }
}

// One thread per (b,t): build (row, weight) list, write mask output.
__global__ void setup_kernel(const void* __restrict__ mask,
                             const void* __restrict__ keep,
                             const float* __restrict__ bj,
                             float* __restrict__ out)
{
    __shared__ int s_mode;
    if (threadIdx.x == 0) s_mode = get_mode();
    __syncthreads();
    int m = s_mode;
    int b = blockIdx.x;
    int t = threadIdx.x;                       // blockDim = 448
    if (t >= NT) return;
    int bt = b * NT + t;

    // ---- mask output ----
    int nidx = (int)floorf((float)t * (512.0f / 426.0f));
    if (nidx > T_IN - 1) nidx = T_IN - 1;
    bool kb = read_bool_m(keep, bt, m);
    bool mo = read_bool_m(mask, b * T_IN + nidx, m) && kb;
    out[XPART + (size_t)bt] = mo ? 1.0f : 0.0f;

    // ---- jitter (scale-then-lerp matches reference rounding) ----
    float jit = 0.0f;
    if (t > 0) {
        float sj = (float)t * (52.0f / 425.0f);
        int ij = (int)floorf(sj);
        if (ij > JF - 2) ij = JF - 2;
        if (ij < 0) ij = 0;
        float fj = sj - (float)ij;
        float j0 = bj[b * JF + ij]     * 0.02f;
        float j1 = bj[b * JF + ij + 1] * 0.02f;
        jit = j0 * (1.0f - fj) + j1 * fj;
    }

    // ---- build (row, weight) list ----
    int   rows[8];
    float wv[8];
    int n = 0;
    int K = g_K[b];

    auto push = [&](int r, float w) {
        for (int i = 0; i < n; i++)
            if (rows[i] == r) { wv[i] += w; return; }
        rows[n] = r; wv[n] = w; n++;
    };
    auto add_x1 = [&](int tau, float c) {
        float s = (float)tau * (511.0f / 425.0f);
        int i0 = (int)floorf(s);
        if (i0 > T_IN - 2) i0 = T_IN - 2;
        if (i0 < 0) i0 = 0;
        float f = s - (float)i0;
        push(i0,     c * (1.0f - f));
        push(i0 + 1, c * f);
    };
    auto add_x2 = [&](int tau, float c) {
        if (read_bool_m(keep, b * NT + tau, m)) {
            add_x1(tau, c);
        } else {
            float s = ((float)tau * (float)(K - 1)) / 425.0f;
            int r0 = (int)floorf(s);
            if (r0 > K - 2) r0 = K - 2;
            if (r0 < 0) r0 = 0;
            float fd = s - (float)r0;
            add_x1(g_keptidx[b][r0],     c * (1.0f - fd));
            add_x1(g_keptidx[b][r0 + 1], c * fd);
        }
    };

    if (t == 0) {
        add_x2(0, 1.0f);
    } else {
        add_x2(t,     1.0f + jit);
        add_x2(t - 1, -jit);
    }
    g_n[bt] = n;
    #pragma unroll
    for (int i = 0; i < 8; i++) {
        g_rows[bt][i] = (i < n) ? rows[i] : 0;
        g_w[bt][i]    = (i < n) ? wv[i]   : 0.0f;
    }
}

// Pure streaming: out[b,t,:] = sum_i w_i * x[b,row_i,:] + noise*.01 + spatial*.005
__global__ __launch_bounds__(256) void fused_kernel(
    const float* __restrict__ x,
    const float* __restrict__ noise,
    const float* __restrict__ sp,
    float* __restrict__ out)
{
    int bt = blockIdx.x;
    int b = bt / NT;

    __shared__ int   srows[8];
    __shared__ float sw[8];
    __shared__ int   snum;

    if (threadIdx.x == 0) snum = g_n[bt];
    if (threadIdx.x < 8) {
        srows[threadIdx.x] = g_rows[bt][threadIdx.x];
        sw[threadIdx.x]    = g_w[bt][threadIdx.x];
    }
    __syncthreads();

    int n = snum;
    const float* xb = x     + (size_t)b * T_IN * NC;
    const float* nz = noise + (size_t)bt * NC;
    const float* sb = sp    + (size_t)b * NC;
    float*       ob = out   + (size_t)bt * NC;

    // 4 consecutive elements per thread -> 4 independent FMA chains, MLP ~ 4n.
    for (int e = threadIdx.x * 4; e < NC; e += 1024) {
        if (e + 3 < NC) {
            float a0 = nz[e]   * 0.01f + sb[e]   * 0.005f;
            float a1 = nz[e+1] * 0.01f + sb[e+1] * 0.005f;
            float a2 = nz[e+2] * 0.01f + sb[e+2] * 0.005f;
            float a3 = nz[e+3] * 0.01f + sb[e+3] * 0.005f;
            for (int i = 0; i < n; i++) {
                const float* xr = xb + (size_t)srows[i] * NC + e;
                float w = sw[i];
                a0 = fmaf(w, xr[0], a0);
                a1 = fmaf(w, xr[1], a1);
                a2 = fmaf(w, xr[2], a2);
                a3 = fmaf(w, xr[3], a3);
            }
            ob[e]   = a0;
            ob[e+1] = a1;
            ob[e+2] = a2;
            ob[e+3] = a3;
        } else {
            for (int k = 0; k < 4; k++) {
                int ee = e + k;
                if (ee < NC) {
                    float a = nz[ee] * 0.01f + sb[ee] * 0.005f;
                    for (int i = 0; i < n; i++)
                        a = fmaf(sw[i], xb[(size_t)srows[i] * NC + ee], a);
                    ob[ee] = a;
                }
            }
        }
    }
}

extern "C" void kernel_launch(void* const* d_in, const int* in_sizes, int n_in,
                              void* d_out, int out_size) {
    const float* x     = (const float*)d_in[0];
    const void*  mask  = d_in[1];
    const void*  keep  = d_in[2];
    const float* bj    = (const float*)d_in[3];
    const float* noise = (const float*)d_in[4];
    const float* sp    = (const float*)d_in[5];
    float* out = (float*)d_out;

    int keep_count = in_sizes[2];                 // BB*NT elements
    reset_kernel<<<1, 1>>>();
    detect_kernel<<<32, 256>>>((const unsigned*)keep, keep_count / 4);
    kept_kernel<<<BB, 448>>>(keep);
    setup_kernel<<<BB, 448>>>(mask, keep, bj, out);
    fused_kernel<<<BB * NT, 256>>>(x, noise, sp, out);
}